// round 2
// baseline (speedup 1.0000x reference)
#include <cuda_runtime.h>

#define BM 64
#define BN 64
#define DH 64
#define PAD 68           // padded smem row stride in floats (4-float aligned, conflict-mitigating)
#define NTHREADS 256

__global__ __launch_bounds__(NTHREADS)
void attn_flash_fp32_kernel(const float* __restrict__ Q,
                            const float* __restrict__ K,
                            const float* __restrict__ V,
                            const int*   __restrict__ mask,
                            float* __restrict__ O,
                            int S) {
    extern __shared__ float smem[];
    float* Qs = smem;                 // [BM][PAD]
    float* Ks = Qs + BM * PAD;        // [BN][PAD]
    float* Vs = Ks + BN * PAD;        // [BN][PAD]
    float* Ps = Vs + BN * PAD;        // [BM][PAD]

    const int tid = threadIdx.x;
    const int tx = tid & 15;          // column group (16 lanes per row-group)
    const int ty = tid >> 4;          // row group
    const int qbase = blockIdx.x * BM;
    const int bh = blockIdx.y;

    const float scale = 0.125f;       // 1/sqrt(64)

    // ---- Load Q tile (BM x DH) into smem, vectorized ----
    {
        const float4* gq = (const float4*)(Q + ((size_t)bh * S + qbase) * DH);
        #pragma unroll
        for (int idx = tid; idx < BM * (DH / 4); idx += NTHREADS) {
            int row = idx >> 4;
            int dg  = idx & 15;
            float4 v = gq[row * (DH / 4) + dg];
            *(float4*)&Qs[row * PAD + dg * 4] = v;
        }
    }

    float m_i[4], l_i[4], o_acc[4][4];
    #pragma unroll
    for (int r = 0; r < 4; r++) {
        m_i[r] = -INFINITY;
        l_i[r] = 0.0f;
        #pragma unroll
        for (int c = 0; c < 4; c++) o_acc[r][c] = 0.0f;
    }

    const int nkt = S / BN;
    for (int kt = 0; kt < nkt; kt++) {
        const int kbase = kt * BN;

        __syncthreads();  // previous iteration's smem reads complete (and Q load on iter 0)

        // ---- Load K,V tiles ----
        {
            const float4* gk = (const float4*)(K + ((size_t)bh * S + kbase) * DH);
            const float4* gv = (const float4*)(V + ((size_t)bh * S + kbase) * DH);
            #pragma unroll
            for (int idx = tid; idx < BN * (DH / 4); idx += NTHREADS) {
                int row = idx >> 4;
                int dg  = idx & 15;
                *(float4*)&Ks[row * PAD + dg * 4] = gk[row * (DH / 4) + dg];
                *(float4*)&Vs[row * PAD + dg * 4] = gv[row * (DH / 4) + dg];
            }
        }

        // ---- Prefetch mask values for this thread's 4x4 (L2-resident) ----
        int mv[4][4];
        #pragma unroll
        for (int r = 0; r < 4; r++) {
            const int qi = qbase + ty + 16 * r;
            const int* mrow = mask + (size_t)qi * S + kbase;
            #pragma unroll
            for (int c = 0; c < 4; c++) mv[r][c] = __ldg(&mrow[tx + 16 * c]);
        }

        __syncthreads();  // K,V visible

        // ---- GEMM1: s = Q K^T (4x4 micro-tile per thread) ----
        float s[4][4];
        #pragma unroll
        for (int r = 0; r < 4; r++)
            #pragma unroll
            for (int c = 0; c < 4; c++) s[r][c] = 0.0f;

        #pragma unroll
        for (int d = 0; d < DH; d += 4) {
            float4 qv[4], kv[4];
            #pragma unroll
            for (int r = 0; r < 4; r++) qv[r] = *(const float4*)&Qs[(ty + 16 * r) * PAD + d];
            #pragma unroll
            for (int c = 0; c < 4; c++) kv[c] = *(const float4*)&Ks[(tx + 16 * c) * PAD + d];
            #pragma unroll
            for (int r = 0; r < 4; r++)
                #pragma unroll
                for (int c = 0; c < 4; c++) {
                    s[r][c] += qv[r].x * kv[c].x;
                    s[r][c] += qv[r].y * kv[c].y;
                    s[r][c] += qv[r].z * kv[c].z;
                    s[r][c] += qv[r].w * kv[c].w;
                }
        }

        // ---- Scale + additive mask + online softmax (per row) ----
        #pragma unroll
        for (int r = 0; r < 4; r++) {
            float mt = -INFINITY;
            #pragma unroll
            for (int c = 0; c < 4; c++) {
                s[r][c] = s[r][c] * scale + (mv[r][c] ? -1.0e9f : 0.0f);
                mt = fmaxf(mt, s[r][c]);
            }
            // row-max over the 16 lanes of this row group
            #pragma unroll
            for (int off = 1; off < 16; off <<= 1)
                mt = fmaxf(mt, __shfl_xor_sync(0xffffffffu, mt, off));

            const float mnew = fmaxf(m_i[r], mt);
            const float alpha = __expf(m_i[r] - mnew);
            m_i[r] = mnew;

            float lsum = 0.0f;
            #pragma unroll
            for (int c = 0; c < 4; c++) {
                float p = __expf(s[r][c] - mnew);
                s[r][c] = p;
                lsum += p;
            }
            #pragma unroll
            for (int off = 1; off < 16; off <<= 1)
                lsum += __shfl_xor_sync(0xffffffffu, lsum, off);

            l_i[r] = l_i[r] * alpha + lsum;
            #pragma unroll
            for (int c = 0; c < 4; c++) o_acc[r][c] *= alpha;
        }

        // ---- Write P tile to smem ----
        #pragma unroll
        for (int r = 0; r < 4; r++)
            #pragma unroll
            for (int c = 0; c < 4; c++)
                Ps[(ty + 16 * r) * PAD + tx + 16 * c] = s[r][c];

        __syncthreads();  // P visible

        // ---- GEMM2: O += P V ----
        #pragma unroll
        for (int j = 0; j < BN; j += 4) {
            float4 pv[4];
            #pragma unroll
            for (int r = 0; r < 4; r++) pv[r] = *(const float4*)&Ps[(ty + 16 * r) * PAD + j];
            #pragma unroll
            for (int jj = 0; jj < 4; jj++) {
                float vv[4];
                #pragma unroll
                for (int c = 0; c < 4; c++) vv[c] = Vs[(j + jj) * PAD + tx + 16 * c];
                #pragma unroll
                for (int r = 0; r < 4; r++) {
                    const float pr = (jj == 0) ? pv[r].x : (jj == 1) ? pv[r].y
                                    : (jj == 2) ? pv[r].z : pv[r].w;
                    #pragma unroll
                    for (int c = 0; c < 4; c++) o_acc[r][c] += pr * vv[c];
                }
            }
        }
    }

    // ---- Epilogue: normalize and store (coalesced over d) ----
    #pragma unroll
    for (int r = 0; r < 4; r++) {
        const int qi = qbase + ty + 16 * r;
        const float inv_l = 1.0f / l_i[r];
        float* orow = O + ((size_t)bh * S + qi) * DH;
        #pragma unroll
        for (int c = 0; c < 4; c++)
            orow[tx + 16 * c] = o_acc[r][c] * inv_l;
    }
}

static int isqrt_exact(long long n) {
    // integer sqrt for S from mask size S*S (S is a multiple of BM here)
    long long lo = 1, hi = 1 << 20;
    while (lo < hi) {
        long long mid = (lo + hi) >> 1;
        if (mid * mid < n) lo = mid + 1; else hi = mid;
    }
    return (int)lo;
}

extern "C" void kernel_launch(void* const* d_in, const int* in_sizes, int n_in,
                              void* d_out, int out_size) {
    const float* Q   = (const float*)d_in[0];
    const float* K   = (const float*)d_in[1];
    const float* V   = (const float*)d_in[2];
    const int*  mask = (const int*)d_in[3];
    float* O = (float*)d_out;

    const int S  = isqrt_exact((long long)in_sizes[3]);   // mask is S*S
    // BH = total Q elements / (S * DH)

    const size_t smem_bytes = (size_t)(BM + BN + BN + BM) * PAD * sizeof(float); // 69632 B
    const int BH = in_sizes[0] / (S * DH);

    cudaFuncSetAttribute(attn_flash_fp32_kernel,
                         cudaFuncAttributeMaxDynamicSharedMemorySize,
                         (int)smem_bytes);

    dim3 grid(S / BM, BH);
    dim3 block(NTHREADS);
    attn_flash_fp32_kernel<<<grid, block, smem_bytes>>>(Q, K, V, mask, O, S);
}

// round 3
// speedup vs baseline: 2.4301x; 2.4301x over previous
#include <cuda_runtime.h>
#include <cuda_bf16.h>

#define BM 64
#define BN 64
#define DH 64
#define PADH 72   // bf16 smem row stride (elements): bank map r*36 ≡ r*4 (mod 32) -> conflict-free frags
#define PADV 72   // V fp32 stride: (k*72+n)%32 = k*8+n -> conflict-free B frags
#define PADP 68   // P fp32 stride: (r*68+k)%32 = r*4+k -> conflict-free A frags
#define NTHREADS 128

__device__ __forceinline__ float to_tf32(float x) {
    float r; asm("cvt.rna.tf32.f32 %0, %1;" : "=f"(r) : "f"(x)); return r;
}

__device__ __forceinline__ unsigned pack_bf2(__nv_bfloat16 a, __nv_bfloat16 b) {
    __nv_bfloat162 t; t.x = a; t.y = b;
    unsigned u; __builtin_memcpy(&u, &t, 4); return u;
}

__device__ __forceinline__ void mma_bf16(float* d, const unsigned* a, const unsigned* b) {
    asm volatile("mma.sync.aligned.m16n8k16.row.col.f32.bf16.bf16.f32 "
        "{%0,%1,%2,%3}, {%4,%5,%6,%7}, {%8,%9}, {%0,%1,%2,%3};"
        : "+f"(d[0]), "+f"(d[1]), "+f"(d[2]), "+f"(d[3])
        : "r"(a[0]), "r"(a[1]), "r"(a[2]), "r"(a[3]), "r"(b[0]), "r"(b[1]));
}

__device__ __forceinline__ void mma_tf32(float* d, const unsigned* a, const unsigned* b) {
    asm volatile("mma.sync.aligned.m16n8k8.row.col.f32.tf32.tf32.f32 "
        "{%0,%1,%2,%3}, {%4,%5,%6,%7}, {%8,%9}, {%0,%1,%2,%3};"
        : "+f"(d[0]), "+f"(d[1]), "+f"(d[2]), "+f"(d[3])
        : "r"(a[0]), "r"(a[1]), "r"(a[2]), "r"(a[3]), "r"(b[0]), "r"(b[1]));
}

__global__ __launch_bounds__(NTHREADS)
void attn_flash_mma_kernel(const float* __restrict__ Q,
                           const float* __restrict__ K,
                           const float* __restrict__ V,
                           const int*   __restrict__ mask,
                           float* __restrict__ O,
                           int S) {
    extern __shared__ char smem_raw[];
    __nv_bfloat16* Qh = (__nv_bfloat16*)smem_raw;                 // [BM][PADH]
    __nv_bfloat16* Ql = Qh + BM * PADH;
    __nv_bfloat16* Kh = Ql + BM * PADH;                           // [BN][PADH]
    __nv_bfloat16* Kl = Kh + BN * PADH;
    float* Vs = (float*)(Kl + BN * PADH);                         // [BN][PADV] (k-major: [key][d])
    float* Ps = Vs + BN * PADV;                                   // [BM][PADP]

    const int tid  = threadIdx.x;
    const int wid  = tid >> 5;
    const int lane = tid & 31;
    const int r    = lane >> 2;       // 0..7
    const int cg   = lane & 3;        // 0..3
    const int wrow = wid * 16;        // warp's 16-row M slice
    const int qbase = blockIdx.x * BM;
    const int bh = blockIdx.y;
    const float scale = 0.125f;       // 1/sqrt(64)

    // ---- Load Q tile once: split into bf16 hi + lo ----
    {
        const float4* gq = (const float4*)(Q + ((size_t)bh * S + qbase) * DH);
        #pragma unroll
        for (int idx = tid; idx < BM * (DH / 4); idx += NTHREADS) {
            int row = idx >> 4, dg = idx & 15;
            float4 v = gq[row * 16 + dg];
            __nv_bfloat16 h0 = __float2bfloat16_rn(v.x);
            __nv_bfloat16 h1 = __float2bfloat16_rn(v.y);
            __nv_bfloat16 h2 = __float2bfloat16_rn(v.z);
            __nv_bfloat16 h3 = __float2bfloat16_rn(v.w);
            __nv_bfloat16 l0 = __float2bfloat16_rn(v.x - __bfloat162float(h0));
            __nv_bfloat16 l1 = __float2bfloat16_rn(v.y - __bfloat162float(h1));
            __nv_bfloat16 l2 = __float2bfloat16_rn(v.z - __bfloat162float(h2));
            __nv_bfloat16 l3 = __float2bfloat16_rn(v.w - __bfloat162float(h3));
            unsigned* ph = (unsigned*)&Qh[row * PADH + dg * 4];
            unsigned* pl = (unsigned*)&Ql[row * PADH + dg * 4];
            ph[0] = pack_bf2(h0, h1); ph[1] = pack_bf2(h2, h3);
            pl[0] = pack_bf2(l0, l1); pl[1] = pack_bf2(l2, l3);
        }
    }

    // per-thread state: rows (wrow+r) and (wrow+r+8)
    float m0 = -INFINITY, m1 = -INFINITY, l0s = 0.0f, l1s = 0.0f;
    float o_acc[8][4];
    #pragma unroll
    for (int nf = 0; nf < 8; nf++)
        #pragma unroll
        for (int c = 0; c < 4; c++) o_acc[nf][c] = 0.0f;

    const int nkt = S / BN;
    for (int kt = 0; kt < nkt; kt++) {
        const int kbase = kt * BN;
        __syncthreads();  // prior-iter smem reads done

        // ---- Load K (split bf16) and V (tf32) tiles ----
        {
            const float4* gk = (const float4*)(K + ((size_t)bh * S + kbase) * DH);
            const float4* gv = (const float4*)(V + ((size_t)bh * S + kbase) * DH);
            #pragma unroll
            for (int idx = tid; idx < BN * (DH / 4); idx += NTHREADS) {
                int row = idx >> 4, dg = idx & 15;
                float4 v = gk[row * 16 + dg];
                __nv_bfloat16 h0 = __float2bfloat16_rn(v.x);
                __nv_bfloat16 h1 = __float2bfloat16_rn(v.y);
                __nv_bfloat16 h2 = __float2bfloat16_rn(v.z);
                __nv_bfloat16 h3 = __float2bfloat16_rn(v.w);
                __nv_bfloat16 q0 = __float2bfloat16_rn(v.x - __bfloat162float(h0));
                __nv_bfloat16 q1 = __float2bfloat16_rn(v.y - __bfloat162float(h1));
                __nv_bfloat16 q2 = __float2bfloat16_rn(v.z - __bfloat162float(h2));
                __nv_bfloat16 q3 = __float2bfloat16_rn(v.w - __bfloat162float(h3));
                unsigned* ph = (unsigned*)&Kh[row * PADH + dg * 4];
                unsigned* pl = (unsigned*)&Kl[row * PADH + dg * 4];
                ph[0] = pack_bf2(h0, h1); ph[1] = pack_bf2(h2, h3);
                pl[0] = pack_bf2(q0, q1); pl[1] = pack_bf2(q2, q3);

                float4 vv = gv[row * 16 + dg];
                float4 vt = { to_tf32(vv.x), to_tf32(vv.y), to_tf32(vv.z), to_tf32(vv.w) };
                *(float4*)&Vs[row * PADV + dg * 4] = vt;
            }
        }
        __syncthreads();  // K,V visible

        // ---- GEMM1: s = Q K^T via bf16 split (3 passes) ----
        float s[8][4];
        #pragma unroll
        for (int nf = 0; nf < 8; nf++)
            #pragma unroll
            for (int c = 0; c < 4; c++) s[nf][c] = 0.0f;

        #pragma unroll
        for (int ks = 0; ks < 4; ks++) {          // k16 steps over DH
            const int kk = ks * 16 + cg * 2;
            unsigned ah[4], al[4];
            ah[0] = *(const unsigned*)&Qh[(wrow + r    ) * PADH + kk];
            ah[1] = *(const unsigned*)&Qh[(wrow + r + 8) * PADH + kk];
            ah[2] = *(const unsigned*)&Qh[(wrow + r    ) * PADH + kk + 8];
            ah[3] = *(const unsigned*)&Qh[(wrow + r + 8) * PADH + kk + 8];
            al[0] = *(const unsigned*)&Ql[(wrow + r    ) * PADH + kk];
            al[1] = *(const unsigned*)&Ql[(wrow + r + 8) * PADH + kk];
            al[2] = *(const unsigned*)&Ql[(wrow + r    ) * PADH + kk + 8];
            al[3] = *(const unsigned*)&Ql[(wrow + r + 8) * PADH + kk + 8];
            #pragma unroll
            for (int nf = 0; nf < 8; nf++) {
                unsigned bh2[2], bl2[2];
                bh2[0] = *(const unsigned*)&Kh[(nf * 8 + r) * PADH + kk];
                bh2[1] = *(const unsigned*)&Kh[(nf * 8 + r) * PADH + kk + 8];
                bl2[0] = *(const unsigned*)&Kl[(nf * 8 + r) * PADH + kk];
                bl2[1] = *(const unsigned*)&Kl[(nf * 8 + r) * PADH + kk + 8];
                mma_bf16(s[nf], ah, bh2);   // hi*hi
                mma_bf16(s[nf], ah, bl2);   // hi*lo
                mma_bf16(s[nf], al, bh2);   // lo*hi
            }
        }

        // ---- scale + mask + online softmax ----
        const int qi0 = qbase + wrow + r;
        const int qi1 = qi0 + 8;
        float mx0 = -INFINITY, mx1 = -INFINITY;
        #pragma unroll
        for (int nf = 0; nf < 8; nf++) {
            const int col = kbase + nf * 8 + cg * 2;
            int2 mr0 = *(const int2*)&mask[(size_t)qi0 * S + col];
            int2 mr1 = *(const int2*)&mask[(size_t)qi1 * S + col];
            s[nf][0] = s[nf][0] * scale + (mr0.x ? -1.0e9f : 0.0f);
            s[nf][1] = s[nf][1] * scale + (mr0.y ? -1.0e9f : 0.0f);
            s[nf][2] = s[nf][2] * scale + (mr1.x ? -1.0e9f : 0.0f);
            s[nf][3] = s[nf][3] * scale + (mr1.y ? -1.0e9f : 0.0f);
            mx0 = fmaxf(mx0, fmaxf(s[nf][0], s[nf][1]));
            mx1 = fmaxf(mx1, fmaxf(s[nf][2], s[nf][3]));
        }
        mx0 = fmaxf(mx0, __shfl_xor_sync(0xffffffffu, mx0, 1));
        mx0 = fmaxf(mx0, __shfl_xor_sync(0xffffffffu, mx0, 2));
        mx1 = fmaxf(mx1, __shfl_xor_sync(0xffffffffu, mx1, 1));
        mx1 = fmaxf(mx1, __shfl_xor_sync(0xffffffffu, mx1, 2));

        const float mn0 = fmaxf(m0, mx0);
        const float mn1 = fmaxf(m1, mx1);
        const float a0 = __expf(m0 - mn0);
        const float a1 = __expf(m1 - mn1);
        m0 = mn0; m1 = mn1;

        float t0 = 0.0f, t1 = 0.0f;
        #pragma unroll
        for (int nf = 0; nf < 8; nf++) {
            float p0 = __expf(s[nf][0] - mn0);
            float p1 = __expf(s[nf][1] - mn0);
            float p2 = __expf(s[nf][2] - mn1);
            float p3 = __expf(s[nf][3] - mn1);
            t0 += p0 + p1; t1 += p2 + p3;
            const int pc = nf * 8 + cg * 2;
            *(float2*)&Ps[(wrow + r    ) * PADP + pc] = make_float2(to_tf32(p0), to_tf32(p1));
            *(float2*)&Ps[(wrow + r + 8) * PADP + pc] = make_float2(to_tf32(p2), to_tf32(p3));
        }
        t0 += __shfl_xor_sync(0xffffffffu, t0, 1);
        t0 += __shfl_xor_sync(0xffffffffu, t0, 2);
        t1 += __shfl_xor_sync(0xffffffffu, t1, 1);
        t1 += __shfl_xor_sync(0xffffffffu, t1, 2);
        l0s = l0s * a0 + t0;
        l1s = l1s * a1 + t1;
        #pragma unroll
        for (int nf = 0; nf < 8; nf++) {
            o_acc[nf][0] *= a0; o_acc[nf][1] *= a0;
            o_acc[nf][2] *= a1; o_acc[nf][3] *= a1;
        }
        __syncwarp();  // warp-private P slab written -> readable

        // ---- GEMM2: O += P V (tf32) ----
        #pragma unroll
        for (int ks = 0; ks < 8; ks++) {          // k8 steps over BN
            unsigned pa[4];
            pa[0] = *(const unsigned*)&Ps[(wrow + r    ) * PADP + ks * 8 + cg];
            pa[1] = *(const unsigned*)&Ps[(wrow + r + 8) * PADP + ks * 8 + cg];
            pa[2] = *(const unsigned*)&Ps[(wrow + r    ) * PADP + ks * 8 + cg + 4];
            pa[3] = *(const unsigned*)&Ps[(wrow + r + 8) * PADP + ks * 8 + cg + 4];
            #pragma unroll
            for (int nf = 0; nf < 8; nf++) {
                unsigned vb[2];
                vb[0] = *(const unsigned*)&Vs[(ks * 8 + cg    ) * PADV + nf * 8 + r];
                vb[1] = *(const unsigned*)&Vs[(ks * 8 + cg + 4) * PADV + nf * 8 + r];
                mma_tf32(o_acc[nf], pa, vb);
            }
        }
        __syncwarp();  // P reads done before next tile's writes
    }

    // ---- Epilogue ----
    const int qi0 = qbase + wrow + r;
    const int qi1 = qi0 + 8;
    const float inv0 = 1.0f / l0s;
    const float inv1 = 1.0f / l1s;
    float* o0 = O + ((size_t)bh * S + qi0) * DH;
    float* o1 = O + ((size_t)bh * S + qi1) * DH;
    #pragma unroll
    for (int nf = 0; nf < 8; nf++) {
        const int col = nf * 8 + cg * 2;
        *(float2*)&o0[col] = make_float2(o_acc[nf][0] * inv0, o_acc[nf][1] * inv0);
        *(float2*)&o1[col] = make_float2(o_acc[nf][2] * inv1, o_acc[nf][3] * inv1);
    }
}

static int isqrt_exact(long long n) {
    long long lo = 1, hi = 1 << 20;
    while (lo < hi) {
        long long mid = (lo + hi) >> 1;
        if (mid * mid < n) lo = mid + 1; else hi = mid;
    }
    return (int)lo;
}

extern "C" void kernel_launch(void* const* d_in, const int* in_sizes, int n_in,
                              void* d_out, int out_size) {
    const float* Q   = (const float*)d_in[0];
    const float* K   = (const float*)d_in[1];
    const float* V   = (const float*)d_in[2];
    const int*  mask = (const int*)d_in[3];
    float* O = (float*)d_out;

    const int S  = isqrt_exact((long long)in_sizes[3]);   // mask is S*S
    const int BH = in_sizes[0] / (S * DH);

    const size_t smem_bytes =
        (size_t)(4 * BM * PADH) * sizeof(__nv_bfloat16) +   // Qh,Ql,Kh,Kl
        (size_t)(BN * PADV) * sizeof(float) +               // V
        (size_t)(BM * PADP) * sizeof(float);                // P   => 72,704 B

    cudaFuncSetAttribute(attn_flash_mma_kernel,
                         cudaFuncAttributeMaxDynamicSharedMemorySize,
                         (int)smem_bytes);

    dim3 grid(S / BM, BH);
    dim3 block(NTHREADS);
    attn_flash_mma_kernel<<<grid, block, smem_bytes>>>(Q, K, V, mask, O, S);
}